// round 1
// baseline (speedup 1.0000x reference)
#include <cuda_runtime.h>
#include <math.h>
#include <stddef.h>

// Problem constants: Dur=32, Dim=256, T=528
#define TT 528

// Scratch (device globals: allocation-free)
__device__ float g_ypart[2][256 * TT];  // conv partial sums, layout [t][o]
__device__ float g_y[256 * TT];         // gelu output, layout [t][o]
__device__ float g_stats[64];           // per-branch {mu, rsig}
__device__ float g_u[TT];
__device__ float g_s1[TT];

// Shared layout for k_conv: xs (32 tau x 128 i-half) + ws (256 rows x (KP+4))
#define XS_FLOATS 4096
#define WS_FLOATS (256 * 36)
#define SMEM_BYTES ((XS_FLOATS + WS_FLOATS) * 4)

// ---------------------------------------------------------------------------
// Stage 1: per-branch conv, templated on (K, L) so everything unrolls.
// Block: 256 threads = 32 o_local x 8 g (i-lanes). Each thread owns 16 i's
// (i = ihalf*128 + ii*8 + g, ii=0..15) and accumulates acc[L] in registers.
// Weights for the 8-i chunk are staged to shared with sector-exact coalesced
// float4 loads (each 128B row touched by one warp-instruction), then read
// back conflict-free (row stride SP = KP+4, SP % 8 == 4).
// ---------------------------------------------------------------------------
template<int K, int L>
__device__ __forceinline__ void conv_branch(
    const float* __restrict__ wB,   // conv_w + b*256*256*32
    const float* __restrict__ xs,   // shared x half  [32][128]
    float* __restrict__ ws,         // shared weight tile
    int otile, int ihalf, int tid,
    float* __restrict__ yout)       // g_ypart[ihalf] + toff*256
{
    constexpr int KP = ((K + 7) / 8) * 8;   // sector-rounded row length
    constexpr int SP = KP + 4;              // shared row stride (conflict-free)
    constexpr int C4 = KP / 4;              // float4 chunks staged per row
    constexpr int NK4 = (K + 3) / 4;        // float4 chunks consumed

    const int o_local = tid >> 3;
    const int g = tid & 7;
    const int o = otile * 32 + o_local;
    const size_t obase = (size_t)o * 8192;  // o * Dim * Dur

    float acc[L];
#pragma unroll
    for (int t = 0; t < L; t++) acc[t] = 0.0f;

    for (int ii = 0; ii < 16; ++ii) {
        __syncthreads();  // previous iteration's readers done with ws
        // ---- cooperative weight staging: 256 rows (32 o x 8 i) of KP floats
        const int ibase = ihalf * 128 + ii * 8;
        for (int idx = tid; idx < 256 * C4; idx += 256) {
            int r = idx / C4;
            int c = idx - r * C4;
            int o_r = r >> 3, g_r = r & 7;
            const float4 v = *reinterpret_cast<const float4*>(
                wB + (size_t)(otile * 32 + o_r) * 8192 + (size_t)(ibase + g_r) * 32 + c * 4);
            *reinterpret_cast<float4*>(ws + r * SP + c * 4) = v;
        }
        __syncthreads();

        // ---- register-cache x column for this thread's i (window = 32 taus)
        const int il = ii * 8 + g;
        float xr[32];
#pragma unroll
        for (int tau = 0; tau < 32; tau++) xr[tau] = xs[tau * 128 + il];

        // ---- register-cache weights (this thread's row = tid)
        float wv[NK4 * 4];
#pragma unroll
        for (int c = 0; c < NK4; c++) {
            float4 w4 = *reinterpret_cast<const float4*>(ws + tid * SP + c * 4);
            wv[c * 4 + 0] = w4.x; wv[c * 4 + 1] = w4.y;
            wv[c * 4 + 2] = w4.z; wv[c * 4 + 3] = w4.w;
        }

        // ---- fully unrolled K*L FMA block
#pragma unroll
        for (int t = 0; t < L; t++) {
#pragma unroll
            for (int h = 0; h < K; h++) {
                acc[t] = fmaf(xr[t + h], wv[h], acc[t]);
            }
        }
    }

    // reduce over the 8 i-lanes (g) via warp shuffles
#pragma unroll
    for (int t = 0; t < L; t++) {
        acc[t] += __shfl_xor_sync(0xffffffffu, acc[t], 1);
        acc[t] += __shfl_xor_sync(0xffffffffu, acc[t], 2);
        acc[t] += __shfl_xor_sync(0xffffffffu, acc[t], 4);
    }
    if (g == 0) {
#pragma unroll
        for (int t = 0; t < L; t++) {
            yout[t * 256 + o] = acc[t];
        }
    }
    (void)obase;
}

template<int B>
__device__ __forceinline__ void dispatch_branch(
    int b, const float* __restrict__ cw, const float* __restrict__ xs,
    float* __restrict__ ws, int otile, int ihalf, int tid)
{
    if (b == B) {
        constexpr int TOFF = B * 32 - (B * (B - 1)) / 2;
        conv_branch<B + 1, 32 - B>(cw + (size_t)B * (256 * 256 * 32),
                                   xs, ws, otile, ihalf, tid,
                                   &g_ypart[ihalf][TOFF * 256]);
    } else if constexpr (B < 31) {
        dispatch_branch<B + 1>(b, cw, xs, ws, otile, ihalf, tid);
    }
}

__global__ void __launch_bounds__(256) k_conv(
    const float* __restrict__ x, const float* __restrict__ cw)
{
    extern __shared__ float smem[];
    float* xs = smem;              // 4096 floats
    float* ws = smem + XS_FLOATS;  // 9216 floats

    const int tid = threadIdx.x;
    const int b = blockIdx.x >> 4;
    const int sub = blockIdx.x & 15;
    const int otile = sub >> 1;
    const int ihalf = sub & 1;

    // stage this block's x half: xs[tau][il] = x[tau*256 + ihalf*128 + il]
    for (int idx = tid; idx < 1024; idx += 256) {
        int tau = idx >> 5;
        int c = idx & 31;
        float4 v = *reinterpret_cast<const float4*>(x + tau * 256 + ihalf * 128 + c * 4);
        *reinterpret_cast<float4*>(xs + tau * 128 + c * 4) = v;
    }
    __syncthreads();

    dispatch_branch<0>(b, cw, xs, ws, otile, ihalf, tid);
}

// ---------------------------------------------------------------------------
// Stage 2: per-branch bias + exact gelu + deterministic mean/var
// ---------------------------------------------------------------------------
__global__ void __launch_bounds__(256) k_stats(const float* __restrict__ conv_b)
{
    const int b = blockIdx.x;
    const int tid = threadIdx.x;
    const int L = 32 - b;
    const int toff = b * 32 - (b * (b - 1)) / 2;
    const int N = 256 * L;
    const float* p0 = &g_ypart[0][toff * 256];
    const float* p1 = &g_ypart[1][toff * 256];
    float* yo = &g_y[toff * 256];
    const float* cb = conv_b + b * 256;

    float s = 0.0f, s2 = 0.0f;
    for (int idx = tid; idx < N; idx += 256) {
        float v = p0[idx] + p1[idx] + cb[idx & 255];
        float ge = 0.5f * v * (1.0f + erff(v * 0.70710678118654752440f));
        yo[idx] = ge;
        s += ge;
        s2 += ge * ge;
    }
    __shared__ float sh[256];
    __shared__ float sh2[256];
    sh[tid] = s; sh2[tid] = s2;
    __syncthreads();
    for (int st = 128; st > 0; st >>= 1) {
        if (tid < st) { sh[tid] += sh[tid + st]; sh2[tid] += sh2[tid + st]; }
        __syncthreads();
    }
    if (tid == 0) {
        float inv = 1.0f / (float)N;
        float mu = sh[0] * inv;
        float var = sh2[0] * inv - mu * mu;
        g_stats[2 * b] = mu;
        g_stats[2 * b + 1] = rsqrtf(var + 1e-5f);
    }
}

// ---------------------------------------------------------------------------
// Stage 3: normalize * ln_w + ln_b, sum over channels -> u[tg]
// ---------------------------------------------------------------------------
__global__ void __launch_bounds__(256) k_unorm(
    const float* __restrict__ lnw, const float* __restrict__ lnb)
{
    const int tg = blockIdx.x;
    const int o = threadIdx.x;
    int b = 0, off = 0;
    while (b < 31 && tg >= off + (32 - b)) { off += (32 - b); ++b; }
    const int tl = tg - off;
    const float mu = g_stats[2 * b];
    const float rs = g_stats[2 * b + 1];
    const int widx = (b * 256 + o) * 32 + tl;
    float val = (g_y[tg * 256 + o] - mu) * rs * lnw[widx] + lnb[widx];

    __shared__ float sh[256];
    sh[o] = val;
    __syncthreads();
    for (int st = 128; st > 0; st >>= 1) {
        if (o < st) sh[o] += sh[o + st];
        __syncthreads();
    }
    if (o == 0) g_u[tg] = sh[0];
}

// ---------------------------------------------------------------------------
// Stage 4: s1[j] = u . in_proj_w[2T + j, :] + 256 * in_proj_b[2T + j]
// ---------------------------------------------------------------------------
__global__ void __launch_bounds__(256) k_s1(
    const float* __restrict__ ipw, const float* __restrict__ ipb)
{
    const int j = blockIdx.x;
    const int tid = threadIdx.x;
    const float* row = ipw + (size_t)(1056 + j) * TT;
    float p = 0.0f;
    for (int t = tid; t < TT; t += 256) p += g_u[t] * row[t];

    __shared__ float sh[256];
    sh[tid] = p;
    __syncthreads();
    for (int st = 128; st > 0; st >>= 1) {
        if (tid < st) sh[tid] += sh[tid + st];
        __syncthreads();
    }
    if (tid == 0) g_s1[j] = sh[0] + 256.0f * ipb[1056 + j];
}

// ---------------------------------------------------------------------------
// Stage 5: out[0,w,d] = (1/32) * sum_j (s1 . out_proj_w[128w+j,:] + 256*opb[128w+j])
// (independent of d -> broadcast over 256 channels)
// ---------------------------------------------------------------------------
__global__ void __launch_bounds__(256) k_out(
    const float* __restrict__ opw, const float* __restrict__ opb,
    float* __restrict__ out)
{
    const int w = blockIdx.x;
    const int tid = threadIdx.x;
    float p = 0.0f;
    for (int q = tid; q < TT; q += 256) {
        float a = 0.0f;
#pragma unroll
        for (int j = 0; j < 32; j++) a += opw[(size_t)(128 * w + j) * TT + q];
        p += g_s1[q] * a;
    }
    if (tid < 32) p += 256.0f * opb[128 * w + tid];

    __shared__ float sh[256];
    sh[tid] = p;
    __syncthreads();
    for (int st = 128; st > 0; st >>= 1) {
        if (tid < st) sh[tid] += sh[tid + st];
        __syncthreads();
    }
    __shared__ float vv;
    if (tid == 0) vv = sh[0] * (1.0f / 32.0f);
    __syncthreads();
    out[w * 256 + tid] = vv;
}

// ---------------------------------------------------------------------------
extern "C" void kernel_launch(void* const* d_in, const int* in_sizes, int n_in,
                              void* d_out, int out_size)
{
    const float* x      = (const float*)d_in[0];
    const float* conv_w = (const float*)d_in[1];
    const float* conv_b = (const float*)d_in[2];
    const float* ln_w   = (const float*)d_in[3];
    const float* ln_b   = (const float*)d_in[4];
    const float* ipw    = (const float*)d_in[5];
    const float* ipb    = (const float*)d_in[6];
    const float* opw    = (const float*)d_in[7];
    const float* opb    = (const float*)d_in[8];
    float* out = (float*)d_out;

    cudaFuncSetAttribute(k_conv, cudaFuncAttributeMaxDynamicSharedMemorySize,
                         SMEM_BYTES);

    k_conv <<<512, 256, SMEM_BYTES>>>(x, conv_w);
    k_stats<<<32, 256>>>(conv_b);
    k_unorm<<<TT, 256>>>(ln_w, ln_b);
    k_s1   <<<TT, 256>>>(ipw, ipb);
    k_out  <<<4, 256>>>(opw, opb, out);

    (void)in_sizes; (void)n_in; (void)out_size;
}

// round 3
// speedup vs baseline: 1.0024x; 1.0024x over previous
#include <cuda_runtime.h>
#include <math.h>
#include <stddef.h>
#include <stdint.h>

// Problem constants: Dur=32, Dim=256, T=528
#define TT 528

// Scratch (device globals: allocation-free)
__device__ float g_ypart[2][256 * TT];  // conv partial sums, layout [t][o]
__device__ float g_stats[64];           // unused (kept for layout stability)
__device__ float g_u[TT];
__device__ float g_s1[TT];

// Shared layout for k_conv: xs (32 tau x 128 i-half) + double-buffered ws
#define XS_FLOATS 4096
#define WSB (256 * 36)                  // one weight buffer (max SP=36)
#define SMEM_BYTES ((XS_FLOATS + 2 * WSB) * 4)

__device__ __forceinline__ uint32_t smem_u32(const void* p) {
    return (uint32_t)__cvta_generic_to_shared(p);
}

// ---------------------------------------------------------------------------
// Stage 1: per-branch conv, templated on (K, L).
// Block: 256 threads = 32 o_local x 8 g (i-lanes). Each thread owns 16 i's
// (i = ihalf*128 + ii*8 + g). Weights staged via cp.async double buffering:
// thread tid owns smem row tid (= its own (o_local,g) weight row), so the
// readback is a private LDS.128 row; staging source ptr is a pure increment.
// ---------------------------------------------------------------------------
template<int K, int L>
__device__ __forceinline__ void conv_branch(
    const float* __restrict__ wB,   // conv_w + b*256*256*32
    const float* __restrict__ xs,   // shared x half  [32][128]
    float* __restrict__ ws,         // shared weight buffers (2 x WSB)
    int otile, int ihalf, int tid,
    float* __restrict__ yout)
{
    constexpr int C4 = (K + 3) / 4;                 // float4 chunks per row
    constexpr int SP = C4 * 4 + ((C4 & 1) ? 8 : 4); // row stride, SP % 8 == 4

    const int g = tid & 7;
    const int o = otile * 32 + (tid >> 3);

    // per-thread staging source: row (o, i0) of this thread; +256 floats per ii
    const float* gsrc = wB + (size_t)o * 8192 + (size_t)(ihalf * 128 + g) * 32;
    const uint32_t sdst0 = smem_u32(ws + tid * SP);
    const uint32_t sdst1 = smem_u32(ws + WSB + tid * SP);

    float acc[L];
#pragma unroll
    for (int t = 0; t < L; t++) acc[t] = 0.0f;

    // prologue: stage ii=0 into buffer 0
#pragma unroll
    for (int c = 0; c < C4; c++) {
        asm volatile("cp.async.cg.shared.global [%0], [%1], 16;"
                     :: "r"(sdst0 + c * 16), "l"(gsrc + c * 4));
    }
    asm volatile("cp.async.commit_group;");

    for (int ii = 0; ii < 16; ++ii) {
        // issue next stage into the other buffer
        if (ii + 1 < 16) {
            const float* src = gsrc + (ii + 1) * 256;
            const uint32_t dst = ((ii + 1) & 1) ? sdst1 : sdst0;
#pragma unroll
            for (int c = 0; c < C4; c++) {
                asm volatile("cp.async.cg.shared.global [%0], [%1], 16;"
                             :: "r"(dst + c * 16), "l"(src + c * 4));
            }
            asm volatile("cp.async.commit_group;");
            asm volatile("cp.async.wait_group 1;");
        } else {
            asm volatile("cp.async.wait_group 0;");
        }
        __syncthreads();   // current buffer visible to all (uniform: all threads stage)

        // register-cache x column for this thread's i (window = K+L-1 = 32)
        const int il = ii * 8 + g;
        float xr[32];
#pragma unroll
        for (int tau = 0; tau < 32; tau++) xr[tau] = xs[tau * 128 + il];

        // register-cache this thread's weight row (private, conflict-free)
        const float* wrow = ws + ((ii & 1) ? WSB : 0) + tid * SP;
        float wv[C4 * 4];
#pragma unroll
        for (int c = 0; c < C4; c++) {
            float4 w4 = *reinterpret_cast<const float4*>(wrow + c * 4);
            wv[c * 4 + 0] = w4.x; wv[c * 4 + 1] = w4.y;
            wv[c * 4 + 2] = w4.z; wv[c * 4 + 3] = w4.w;
        }

        // fully unrolled K*L FMA block
#pragma unroll
        for (int t = 0; t < L; t++) {
#pragma unroll
            for (int h = 0; h < K; h++) {
                acc[t] = fmaf(xr[t + h], wv[h], acc[t]);
            }
        }
        __syncthreads();   // everyone done reading this buffer before reuse
    }

    // reduce over the 8 i-lanes via warp shuffles
#pragma unroll
    for (int t = 0; t < L; t++) {
        acc[t] += __shfl_xor_sync(0xffffffffu, acc[t], 1);
        acc[t] += __shfl_xor_sync(0xffffffffu, acc[t], 2);
        acc[t] += __shfl_xor_sync(0xffffffffu, acc[t], 4);
    }
    if (g == 0) {
#pragma unroll
        for (int t = 0; t < L; t++) yout[t * 256 + o] = acc[t];
    }
}

template<int B>
__device__ __forceinline__ void dispatch_branch(
    int b, const float* __restrict__ cw, const float* __restrict__ xs,
    float* __restrict__ ws, int otile, int ihalf, int tid)
{
    if (b == B) {
        constexpr int TOFF = B * 32 - (B * (B - 1)) / 2;
        conv_branch<B + 1, 32 - B>(cw + (size_t)B * (256 * 256 * 32),
                                   xs, ws, otile, ihalf, tid,
                                   &g_ypart[ihalf][TOFF * 256]);
    } else if constexpr (B < 31) {
        dispatch_branch<B + 1>(b, cw, xs, ws, otile, ihalf, tid);
    }
}

__global__ void __launch_bounds__(256) k_conv(
    const float* __restrict__ x, const float* __restrict__ cw)
{
    extern __shared__ float smem[];
    float* xs = smem;
    float* ws = smem + XS_FLOATS;

    const int tid = threadIdx.x;
    const int b = blockIdx.x >> 4;
    const int sub = blockIdx.x & 15;
    const int otile = sub >> 1;
    const int ihalf = sub & 1;

    // stage this block's x half: xs[tau][il] = x[tau*256 + ihalf*128 + il]
    for (int idx = tid; idx < 1024; idx += 256) {
        int tau = idx >> 5;
        int c = idx & 31;
        float4 v = *reinterpret_cast<const float4*>(x + tau * 256 + ihalf * 128 + c * 4);
        *reinterpret_cast<float4*>(xs + tau * 128 + c * 4) = v;
    }
    __syncthreads();

    dispatch_branch<0>(b, cw, xs, ws, otile, ihalf, tid);
}

// ---------------------------------------------------------------------------
// Stage 2 (fused): per-branch bias + exact gelu + mean/var + ln + channel-sum.
// 32 blocks x 256 threads; thread tid owns channel o = tid for all t in [0,L).
// gelu values live in registers across both reductions.
// ---------------------------------------------------------------------------
__global__ void __launch_bounds__(256) k_post(
    const float* __restrict__ conv_b,
    const float* __restrict__ lnw, const float* __restrict__ lnb)
{
    const int b = blockIdx.x;
    const int tid = threadIdx.x;
    const int L = 32 - b;
    const int toff = b * 32 - (b * (b - 1)) / 2;
    const int o = tid;

    const float* p0 = &g_ypart[0][toff * 256 + o];
    const float* p1 = &g_ypart[1][toff * 256 + o];
    const float cb = conv_b[b * 256 + o];

    float v[32];
    float s = 0.0f, s2 = 0.0f;
#pragma unroll
    for (int t = 0; t < 32; t++) {
        if (t < L) {
            float val = p0[t * 256] + p1[t * 256] + cb;
            float ge = 0.5f * val * (1.0f + erff(val * 0.70710678118654752440f));
            v[t] = ge;
            s += ge;
            s2 += ge * ge;
        }
    }

    __shared__ float sh[256];
    __shared__ float sh2[256];
    sh[tid] = s; sh2[tid] = s2;
    __syncthreads();
    for (int st = 128; st > 0; st >>= 1) {
        if (tid < st) { sh[tid] += sh[tid + st]; sh2[tid] += sh2[tid + st]; }
        __syncthreads();
    }
    __shared__ float s_mu, s_rs;
    if (tid == 0) {
        float inv = 1.0f / (float)(256 * L);
        float mu = sh[0] * inv;
        float var = sh2[0] * inv - mu * mu;
        s_mu = mu;
        s_rs = rsqrtf(var + 1e-5f);
    }
    __syncthreads();
    const float mu = s_mu, rs = s_rs;

    // u[toff+t] = sum_o ( (v[t]-mu)*rs*lnw[b,o,t] + lnb[b,o,t] )
    const float* lwp = lnw + ((size_t)b * 256 + o) * 32;
    const float* lbp = lnb + ((size_t)b * 256 + o) * 32;
    const int warp = tid >> 5, lane = tid & 31;
    __shared__ float red[32][9];

#pragma unroll
    for (int t = 0; t < 32; t++) {
        float c = 0.0f;
        if (t < L) c = fmaf((v[t] - mu) * rs, lwp[t], lbp[t]);
        c += __shfl_xor_sync(0xffffffffu, c, 16);
        c += __shfl_xor_sync(0xffffffffu, c, 8);
        c += __shfl_xor_sync(0xffffffffu, c, 4);
        c += __shfl_xor_sync(0xffffffffu, c, 2);
        c += __shfl_xor_sync(0xffffffffu, c, 1);
        if (lane == 0) red[t][warp] = c;
    }
    __syncthreads();
    if (tid < L) {
        float u = 0.0f;
#pragma unroll
        for (int w = 0; w < 8; w++) u += red[tid][w];
        g_u[toff + tid] = u;
    }
}

// ---------------------------------------------------------------------------
// Stage 3: s1[j] = u . in_proj_w[2T + j, :] + 256 * in_proj_b[2T + j]
// 66 blocks x 8 warps; one warp per output row, u cached in smem.
// ---------------------------------------------------------------------------
__global__ void __launch_bounds__(256) k_s1(
    const float* __restrict__ ipw, const float* __restrict__ ipb)
{
    const int tid = threadIdx.x;
    const int warp = tid >> 5, lane = tid & 31;
    const int j = blockIdx.x * 8 + warp;

    __shared__ float us[TT];
    for (int t = tid; t < TT; t += 256) us[t] = g_u[t];
    __syncthreads();

    const float* row = ipw + (size_t)(2 * TT + j) * TT;
    float p = 0.0f;
    for (int t = lane; t < TT; t += 32) p += us[t] * row[t];
    p += __shfl_xor_sync(0xffffffffu, p, 16);
    p += __shfl_xor_sync(0xffffffffu, p, 8);
    p += __shfl_xor_sync(0xffffffffu, p, 4);
    p += __shfl_xor_sync(0xffffffffu, p, 2);
    p += __shfl_xor_sync(0xffffffffu, p, 1);
    if (lane == 0) g_s1[j] = p + 256.0f * ipb[2 * TT + j];
}

// ---------------------------------------------------------------------------
// Stage 4: out[0,w,d] = (1/32) * sum_{j<32} (s1 . opw[128w+j,:] + 256*opb[128w+j])
// (independent of d -> broadcast over 256 channels)
// ---------------------------------------------------------------------------
__global__ void __launch_bounds__(256) k_out(
    const float* __restrict__ opw, const float* __restrict__ opb,
    float* __restrict__ out)
{
    const int w = blockIdx.x;
    const int tid = threadIdx.x;
    float p = 0.0f;
    for (int q = tid; q < TT; q += 256) {
        float a = 0.0f;
#pragma unroll
        for (int j = 0; j < 32; j++) a += opw[(size_t)(128 * w + j) * TT + q];
        p += g_s1[q] * a;
    }
    if (tid < 32) p += 256.0f * opb[128 * w + tid];

    __shared__ float sh[256];
    sh[tid] = p;
    __syncthreads();
    for (int st = 128; st > 0; st >>= 1) {
        if (tid < st) sh[tid] += sh[tid + st];
        __syncthreads();
    }
    __shared__ float vv;
    if (tid == 0) vv = sh[0] * (1.0f / 32.0f);
    __syncthreads();
    out[w * 256 + tid] = vv;
}

// ---------------------------------------------------------------------------
extern "C" void kernel_launch(void* const* d_in, const int* in_sizes, int n_in,
                              void* d_out, int out_size)
{
    const float* x      = (const float*)d_in[0];
    const float* conv_w = (const float*)d_in[1];
    const float* conv_b = (const float*)d_in[2];
    const float* ln_w   = (const float*)d_in[3];
    const float* ln_b   = (const float*)d_in[4];
    const float* ipw    = (const float*)d_in[5];
    const float* ipb    = (const float*)d_in[6];
    const float* opw    = (const float*)d_in[7];
    const float* opb    = (const float*)d_in[8];
    float* out = (float*)d_out;

    cudaFuncSetAttribute(k_conv, cudaFuncAttributeMaxDynamicSharedMemorySize,
                         SMEM_BYTES);

    k_conv<<<512, 256, SMEM_BYTES>>>(x, conv_w);
    k_post<<<32, 256>>>(conv_b, ln_w, ln_b);
    k_s1  <<<66, 256>>>(ipw, ipb);
    k_out <<<4, 256>>>(opw, opb, out);

    (void)in_sizes; (void)n_in; (void)out_size;
}

// round 4
// speedup vs baseline: 1.1185x; 1.1158x over previous
#include <cuda_runtime.h>
#include <math.h>
#include <stddef.h>
#include <stdint.h>

// Problem constants: Dur=32, Dim=256, T=528
#define TT 528

// Scratch (device globals: allocation-free)
__device__ float g_ypart[2][256 * TT];  // conv partial sums, layout [t][o]
__device__ float g_u[TT];
__device__ float g_a[4 * TT];           // a_w[q] = col-sums of opw rows 128w..128w+31
__device__ float g_p[4 * TT];           // p_w[q] = a_w[q] * s1full[q]

// Shared layout for k_conv: xs (32 tau x 128 i-half) + double-buffered ws
#define XS_FLOATS 4096
#define WSB (256 * 36)                  // one weight buffer (max SP=36)
#define SMEM_BYTES ((XS_FLOATS + 2 * WSB) * 4)

__device__ __forceinline__ uint32_t smem_u32(const void* p) {
    return (uint32_t)__cvta_generic_to_shared(p);
}
__device__ __forceinline__ unsigned long long pk2(float lo, float hi) {
    unsigned long long r;
    asm("mov.b64 %0, {%1, %2};" : "=l"(r) : "f"(lo), "f"(hi));
    return r;
}
__device__ __forceinline__ void upk2(float& lo, float& hi, unsigned long long v) {
    asm("mov.b64 {%0, %1}, %2;" : "=f"(lo), "=f"(hi) : "l"(v));
}
__device__ __forceinline__ void fma2(unsigned long long& d,
                                     unsigned long long a, unsigned long long b) {
    asm("fma.rn.f32x2 %0, %1, %2, %0;" : "+l"(d) : "l"(a), "l"(b));
}

// ---------------------------------------------------------------------------
// Stage 1: per-branch conv, templated on (K, L), f32x2 packed over t-pairs.
// Block: 256 threads = 32 o x 8 g (i-lanes). Each thread owns 16 i's.
// Weights staged coalesced via cp.async double buffering.
// ---------------------------------------------------------------------------
template<int K, int L>
__device__ __forceinline__ void conv_branch(
    const float* __restrict__ wB,   // conv_w + b*256*256*32
    const float* __restrict__ xs,   // shared x half  [32][128]
    float* __restrict__ ws,         // shared weight buffers (2 x WSB)
    int otile, int ihalf, int tid,
    float* __restrict__ yout)
{
    constexpr int C4 = (K + 3) / 4;                 // float4 chunks per row
    constexpr int SP = C4 * 4 + ((C4 & 1) ? 8 : 4); // row stride, SP % 8 == 4
    constexpr int L2 = L / 2;                       // packed t-pairs

    const int g = tid & 7;
    const int o = otile * 32 + (tid >> 3);

    // coalesced staging: thread handles chunks idx = tid + 256*k of 256*C4
    // row r = idx / C4 (o_r = r>>3, g_r = r&7), chunk c = idx % C4
    const int r0 = tid / C4;
    const int c0 = tid - r0 * C4;

    unsigned long long acc2[L2 > 0 ? L2 : 1];
#pragma unroll
    for (int t = 0; t < L2; t++) acc2[t] = 0ull;
    float accT = 0.0f;  // tail row (odd L)

    // ---- staging helper (issues C4 cp.asyncs per thread, coalesced) ----
    auto stage = [&](int ii, int buf) {
        const int ibase = ihalf * 128 + ii * 8;
        const uint32_t wsb = smem_u32(ws + buf * WSB);
#pragma unroll
        for (int k = 0; k < C4; k++) {
            int idx = tid + 256 * k;
            int r = idx / C4;
            int c = idx - r * C4;
            const float* src = wB + (size_t)(otile * 32 + (r >> 3)) * 8192
                                  + (size_t)(ibase + (r & 7)) * 32 + c * 4;
            asm volatile("cp.async.cg.shared.global [%0], [%1], 16;"
                         :: "r"(wsb + (r * SP + c * 4) * 4), "l"(src));
        }
        asm volatile("cp.async.commit_group;");
    };

    stage(0, 0);

    for (int ii = 0; ii < 16; ++ii) {
        if (ii + 1 < 16) {
            stage(ii + 1, (ii + 1) & 1);
            asm volatile("cp.async.wait_group 1;");
        } else {
            asm volatile("cp.async.wait_group 0;");
        }
        __syncthreads();

        // x column for this thread's i: pack even/odd adjacent pairs
        const int il = ii * 8 + g;
        const float* xcol = xs + il;
        unsigned long long xe[16], xo[15];
        if constexpr (L2 > 0) {
            float prev_b = 0.0f;
#pragma unroll
            for (int k = 0; k < 16; k++) {
                float a = xcol[(2 * k) * 128];
                float bb = xcol[(2 * k + 1) * 128];
                xe[k] = pk2(a, bb);
                if (k > 0) xo[k - 1] = pk2(prev_b, a);
                prev_b = bb;
            }
        }

        // register-cache this thread's weight row (private, conflict-free)
        const float* wrow = ws + ((ii & 1) ? WSB : 0) + tid * SP;
        float wv[C4 * 4];
#pragma unroll
        for (int c = 0; c < C4; c++) {
            float4 w4 = *reinterpret_cast<const float4*>(wrow + c * 4);
            wv[c * 4 + 0] = w4.x; wv[c * 4 + 1] = w4.y;
            wv[c * 4 + 2] = w4.z; wv[c * 4 + 3] = w4.w;
        }
        unsigned long long ww[K];
#pragma unroll
        for (int h = 0; h < K; h++) ww[h] = pk2(wv[h], wv[h]);

        // packed K*L/2 f32x2 FMA block
#pragma unroll
        for (int tp = 0; tp < L2; tp++) {
#pragma unroll
            for (int h = 0; h < K; h++) {
                if ((h & 1) == 0) fma2(acc2[tp], xe[tp + h / 2], ww[h]);
                else              fma2(acc2[tp], xo[tp + (h - 1) / 2], ww[h]);
            }
        }
        if constexpr (L & 1) {  // scalar tail row t = L-1
#pragma unroll
            for (int h = 0; h < K; h++)
                accT = fmaf(xcol[(L - 1 + h) * 128], wv[h], accT);
        }
        __syncthreads();
    }

    // unpack, reduce over the 8 i-lanes via warp shuffles, store
#pragma unroll
    for (int tp = 0; tp < L2; tp++) {
        float a0, a1;
        upk2(a0, a1, acc2[tp]);
#pragma unroll
        for (int m = 1; m <= 4; m <<= 1) {
            a0 += __shfl_xor_sync(0xffffffffu, a0, m);
            a1 += __shfl_xor_sync(0xffffffffu, a1, m);
        }
        if (g == 0) {
            yout[(2 * tp) * 256 + o] = a0;
            yout[(2 * tp + 1) * 256 + o] = a1;
        }
    }
    if constexpr (L & 1) {
#pragma unroll
        for (int m = 1; m <= 4; m <<= 1)
            accT += __shfl_xor_sync(0xffffffffu, accT, m);
        if (g == 0) yout[(L - 1) * 256 + o] = accT;
    }
}

template<int B>
__device__ __forceinline__ void dispatch_branch(
    int b, const float* __restrict__ cw, const float* __restrict__ xs,
    float* __restrict__ ws, int otile, int ihalf, int tid)
{
    if (b == B) {
        constexpr int TOFF = B * 32 - (B * (B - 1)) / 2;
        conv_branch<B + 1, 32 - B>(cw + (size_t)B * (256 * 256 * 32),
                                   xs, ws, otile, ihalf, tid,
                                   &g_ypart[ihalf][TOFF * 256]);
    } else if constexpr (B < 31) {
        dispatch_branch<B + 1>(b, cw, xs, ws, otile, ihalf, tid);
    }
}

__global__ void __launch_bounds__(256) k_conv(
    const float* __restrict__ x, const float* __restrict__ cw)
{
    extern __shared__ float smem[];
    float* xs = smem;
    float* ws = smem + XS_FLOATS;

    const int tid = threadIdx.x;
    const int ko = blockIdx.x >> 4;
    // heavy-first: K*L = (b+1)(32-b) is max at b=15,16 -> schedule those first
    const int b = (ko & 1) ? (16 + (ko >> 1)) : (15 - (ko >> 1));
    const int sub = blockIdx.x & 15;
    const int otile = sub >> 1;
    const int ihalf = sub & 1;

    for (int idx = tid; idx < 1024; idx += 256) {
        int tau = idx >> 5;
        int c = idx & 31;
        float4 v = *reinterpret_cast<const float4*>(x + tau * 256 + ihalf * 128 + c * 4);
        *reinterpret_cast<float4*>(xs + tau * 128 + c * 4) = v;
    }
    __syncthreads();

    dispatch_branch<0>(b, cw, xs, ws, otile, ihalf, tid);
}

// ---------------------------------------------------------------------------
// Stage 2 (fused): per-branch bias + exact gelu + mean/var + ln + channel-sum.
// ---------------------------------------------------------------------------
__global__ void __launch_bounds__(256) k_post(
    const float* __restrict__ conv_b,
    const float* __restrict__ lnw, const float* __restrict__ lnb)
{
    const int b = blockIdx.x;
    const int tid = threadIdx.x;
    const int L = 32 - b;
    const int toff = b * 32 - (b * (b - 1)) / 2;
    const int o = tid;

    const float* p0 = &g_ypart[0][toff * 256 + o];
    const float* p1 = &g_ypart[1][toff * 256 + o];
    const float cb = conv_b[b * 256 + o];

    float v[32];
    float s = 0.0f, s2 = 0.0f;
#pragma unroll
    for (int t = 0; t < 32; t++) {
        if (t < L) {
            float val = p0[t * 256] + p1[t * 256] + cb;
            float ge = 0.5f * val * (1.0f + erff(val * 0.70710678118654752440f));
            v[t] = ge;
            s += ge;
            s2 += ge * ge;
        }
    }

    __shared__ float sh[256];
    __shared__ float sh2[256];
    sh[tid] = s; sh2[tid] = s2;
    __syncthreads();
    for (int st = 128; st > 0; st >>= 1) {
        if (tid < st) { sh[tid] += sh[tid + st]; sh2[tid] += sh2[tid + st]; }
        __syncthreads();
    }
    __shared__ float s_mu, s_rs;
    if (tid == 0) {
        float inv = 1.0f / (float)(256 * L);
        float mu = sh[0] * inv;
        float var = sh2[0] * inv - mu * mu;
        s_mu = mu;
        s_rs = rsqrtf(var + 1e-5f);
    }
    __syncthreads();
    const float mu = s_mu, rs = s_rs;

    const float* lwp = lnw + ((size_t)b * 256 + o) * 32;
    const float* lbp = lnb + ((size_t)b * 256 + o) * 32;
    const int warp = tid >> 5, lane = tid & 31;
    __shared__ float red[32][9];

#pragma unroll
    for (int t = 0; t < 32; t++) {
        float c = 0.0f;
        if (t < L) c = fmaf((v[t] - mu) * rs, lwp[t], lbp[t]);
        c += __shfl_xor_sync(0xffffffffu, c, 16);
        c += __shfl_xor_sync(0xffffffffu, c, 8);
        c += __shfl_xor_sync(0xffffffffu, c, 4);
        c += __shfl_xor_sync(0xffffffffu, c, 2);
        c += __shfl_xor_sync(0xffffffffu, c, 1);
        if (lane == 0) red[t][warp] = c;
    }
    __syncthreads();
    if (tid < L) {
        float u = 0.0f;
#pragma unroll
        for (int w = 0; w < 8; w++) u += red[tid][w];
        g_u[toff + tid] = u;
    }
}

// ---------------------------------------------------------------------------
// k_pre (independent of conv): a_w[q] = sum_{j<32} opw[128w+j, q]
// grid 8 = (w, q-half); coalesced over q.
// ---------------------------------------------------------------------------
__global__ void __launch_bounds__(256) k_pre(const float* __restrict__ opw)
{
    const int w = blockIdx.x >> 1;
    const int half = blockIdx.x & 1;
    const int tid = threadIdx.x;
    for (int qi = tid; qi < 264; qi += 256) {
        int q = half * 264 + qi;
        float a = 0.0f;
        const float* base = opw + (size_t)(128 * w) * TT + q;
#pragma unroll
        for (int j = 0; j < 32; j++) a += base[(size_t)j * TT];
        g_a[w * TT + q] = a;
    }
}

// ---------------------------------------------------------------------------
// k_mid: per-q  s1full[q] = u . ipw[2T+q,:] + 256*ipb[2T+q];
//        p_w[q] = a_w[q] * s1full[q].  132 blocks x 4 warps (warp per q).
// ---------------------------------------------------------------------------
__global__ void __launch_bounds__(128) k_mid(
    const float* __restrict__ ipw, const float* __restrict__ ipb)
{
    const int tid = threadIdx.x;
    const int warp = tid >> 5, lane = tid & 31;
    const int q = blockIdx.x * 4 + warp;

    __shared__ float us[TT];
    for (int t = tid; t < TT; t += 128) us[t] = g_u[t];
    __syncthreads();

    const float* row = ipw + (size_t)(2 * TT + q) * TT;
    float p = 0.0f;
#pragma unroll 4
    for (int t = lane; t < TT; t += 32) p += us[t] * row[t];
    p += __shfl_xor_sync(0xffffffffu, p, 16);
    p += __shfl_xor_sync(0xffffffffu, p, 8);
    p += __shfl_xor_sync(0xffffffffu, p, 4);
    p += __shfl_xor_sync(0xffffffffu, p, 2);
    p += __shfl_xor_sync(0xffffffffu, p, 1);
    if (lane == 0) {
        float s1f = p + 256.0f * ipb[2 * TT + q];
#pragma unroll
        for (int w = 0; w < 4; w++) g_p[w * TT + q] = g_a[w * TT + q] * s1f;
    }
}

// ---------------------------------------------------------------------------
// k_fin: out[0,w,d] = (1/32) * ( sum_q p_w[q] + 256 * sum_{j<32} opb[128w+j] )
// ---------------------------------------------------------------------------
__global__ void __launch_bounds__(256) k_fin(
    const float* __restrict__ opb, float* __restrict__ out)
{
    const int tid = threadIdx.x;
    __shared__ float sh[256];
    __shared__ float tot[4];
#pragma unroll
    for (int w = 0; w < 4; w++) {
        float p = 0.0f;
        for (int q = tid; q < TT; q += 256) p += g_p[w * TT + q];
        if (tid < 32) p += 256.0f * opb[128 * w + tid];
        sh[tid] = p;
        __syncthreads();
        for (int st = 128; st > 0; st >>= 1) {
            if (tid < st) sh[tid] += sh[tid + st];
            __syncthreads();
        }
        if (tid == 0) tot[w] = sh[0] * (1.0f / 32.0f);
        __syncthreads();
    }
#pragma unroll
    for (int w = 0; w < 4; w++) out[w * 256 + tid] = tot[w];
}

// ---------------------------------------------------------------------------
extern "C" void kernel_launch(void* const* d_in, const int* in_sizes, int n_in,
                              void* d_out, int out_size)
{
    const float* x      = (const float*)d_in[0];
    const float* conv_w = (const float*)d_in[1];
    const float* conv_b = (const float*)d_in[2];
    const float* ln_w   = (const float*)d_in[3];
    const float* ln_b   = (const float*)d_in[4];
    const float* ipw    = (const float*)d_in[5];
    const float* ipb    = (const float*)d_in[6];
    const float* opw    = (const float*)d_in[7];
    const float* opb    = (const float*)d_in[8];
    float* out = (float*)d_out;

    cudaFuncSetAttribute(k_conv, cudaFuncAttributeMaxDynamicSharedMemorySize,
                         SMEM_BYTES);

    k_pre <<<8, 256>>>(opw);
    k_conv<<<512, 256, SMEM_BYTES>>>(x, conv_w);
    k_post<<<32, 256>>>(conv_b, ln_w, ln_b);
    k_mid <<<132, 128>>>(ipw, ipb);
    k_fin <<<1, 256>>>(opb, out);

    (void)in_sizes; (void)n_in; (void)out_size;
}